// round 10
// baseline (speedup 1.0000x reference)
#include <cuda_runtime.h>

#define B_ 256
#define T_ 1024
#define K_ 128
#define LN2 0.69314718055994531f

__device__ float g_logz[B_];
__device__ float g_gold[B_];

__device__ __forceinline__ void fma2(unsigned long long &acc, unsigned long long a, unsigned long long b) {
    asm("fma.rn.f32x2 %0, %1, %2, %0;" : "+l"(acc) : "l"(a), "l"(b));
}
__device__ __forceinline__ unsigned long long add2(unsigned long long a, unsigned long long b) {
    unsigned long long c;
    asm("add.rn.f32x2 %0, %1, %2;" : "=l"(c) : "l"(a), "l"(b));
    return c;
}
__device__ __forceinline__ unsigned long long pack2(float x, float y) {
    unsigned long long r;
    asm("mov.b64 %0, {%1, %2};" : "=l"(r) : "f"(x), "f"(y));
    return r;
}
__device__ __forceinline__ float2 unpack2(unsigned long long v) {
    float2 f;
    asm("mov.b64 {%0, %1}, %2;" : "=f"(f.x), "=f"(f.y) : "l"(v));
    return f;
}
__device__ __forceinline__ float warp_sum(float v) {
    #pragma unroll
    for (int o = 16; o > 0; o >>= 1) v += __shfl_xor_sync(0xffffffffu, v, o);
    return v;
}

// Fused kernel: blocks [0,256) run the forward logZ scan; blocks [256,512)
// run the (short, LDG-bound) gold-score — those drain through the spare
// occupancy slots while the forward scan runs, so they cost ~nothing.
//
// Forward: exp domain, p_t = (p_{t-1} @ E) * exp(em_t) * 2^-ke, masked;
// ke = exponent(p_{t-1}[0]) peeked from the first GEMV LDS (CTA-uniform).
// Thread j owns state j; E column in 64 packed f32x2 regs; one barrier/step.
// Masks via one int4 per 4 steps; branchless clamped prefetch; exp prefetch
// placed between the FMA block and the dependency tail.
__global__ __launch_bounds__(128, 2) void crf_main(
    const float* __restrict__ emis,   // (B,T,K)
    const int* __restrict__ tags,     // (B,T) int32
    const int* __restrict__ mask,     // (B,T) int32
    const float* __restrict__ start,  // (K)
    const float* __restrict__ endv,   // (K)
    const float* __restrict__ trans)  // (K,K)
{
    __shared__ __align__(16) float pb0[K_];
    __shared__ __align__(16) float pb1[K_];
    __shared__ float wred[4];
    __shared__ int wcn[4];

    if (blockIdx.x >= B_) {
        // ---------------- gold path ----------------
        const int b = blockIdx.x - B_;
        const int tid = threadIdx.x;
        const float* __restrict__ eb = emis + (size_t)b * T_ * K_;
        const int* __restrict__ tg = tags + (size_t)b * T_;
        const int* __restrict__ mb = mask + (size_t)b * T_;

        float sc = 0.0f;
        int cnt = 0;
        for (int t = tid; t < T_; t += 128) {
            int mt = mb[t];
            cnt += mt ? 1 : 0;
            if (t >= 1 && mt && mb[t - 1]) {
                int pr = tg[t - 1]; pr = pr < 0 ? 0 : pr;
                int cr = tg[t];     cr = cr < 0 ? 0 : cr;
                sc += trans[pr * K_ + cr] + eb[(size_t)t * K_ + cr];
            }
        }
        float s = warp_sum(sc);
        int c = cnt;
        #pragma unroll
        for (int o = 16; o > 0; o >>= 1) c += __shfl_xor_sync(0xffffffffu, c, o);
        if ((tid & 31) == 0) { wred[tid >> 5] = s; wcn[tid >> 5] = c; }
        __syncthreads();
        if (tid == 0) {
            float total = (wred[0] + wred[1]) + (wred[2] + wred[3]);
            int ctot = wcn[0] + wcn[1] + wcn[2] + wcn[3];
            int t0 = tg[0];
            float sc0 = (start[t0] + eb[t0]) * (mb[0] ? 1.0f : 0.0f);
            int last = tg[ctot - 1];
            g_gold[b] = total + sc0 + endv[last];
        }
        return;
    }

    // ---------------- forward path ----------------
    const int b = blockIdx.x;
    const int j = threadIdx.x;

    // E[:,j] packed over i-pairs
    unsigned long long e2[K_ / 2];
    #pragma unroll
    for (int k = 0; k < K_ / 2; ++k) {
        float ea  = __expf(trans[(2 * k) * K_ + j]);
        float ebv = __expf(trans[(2 * k + 1) * K_ + j]);
        e2[k] = pack2(ea, ebv);
    }

    const float* __restrict__ eb = emis + (size_t)b * T_ * K_;
    const int* __restrict__ mb = mask + (size_t)b * T_;

    float p = __expf(start[j] + eb[j]);  // t = 0
    int kacc = 0;
    pb0[j] = p;

    // 3-deep exp prefetch; scalar masks for steps 1..3; int4 for block t=4..7
    float eA = __expf(eb[1 * K_ + j]);
    float eB = __expf(eb[2 * K_ + j]);
    float eC = __expf(eb[3 * K_ + j]);
    int m1 = mb[1], m2 = mb[2], m3 = mb[3];
    int4 mk4 = *(const int4*)(mb + 4);
    __syncthreads();

#define CRF_STEP(T_IDX, PRD, PWR, MK, POST)                                   \
    {                                                                         \
        float eem = eA; eA = eB; eB = eC;                                     \
        int mk = (MK);                                                        \
        const ulonglong2* __restrict__ pv = (const ulonglong2*)(PRD);         \
        ulonglong2 q0 = pv[0];                                                \
        float2 f0 = unpack2(q0.x);                                            \
        unsigned int xb = __float_as_uint(f0.x) >> 23;                        \
        int ke = (int)xb - 127;                                               \
        float scale = __uint_as_float((254u - xb) << 23);  /* 2^-ke exact */  \
        if (!mk) { ke = 0; scale = 1.0f; }                                    \
        float eemx = eem * scale;                                             \
        kacc += ke;                                                           \
        unsigned long long a0 = 0ull, a1 = 0ull, a2 = 0ull, a3 = 0ull;        \
        unsigned long long a4 = 0ull, a5 = 0ull, a6 = 0ull, a7 = 0ull;        \
        ulonglong2 q1 = pv[1];                                                \
        ulonglong2 q2 = pv[2];                                                \
        ulonglong2 q3 = pv[3];                                                \
        fma2(a0, q0.x, e2[0]); fma2(a1, q0.y, e2[1]);                         \
        fma2(a2, q1.x, e2[2]); fma2(a3, q1.y, e2[3]);                         \
        fma2(a4, q2.x, e2[4]); fma2(a5, q2.y, e2[5]);                         \
        fma2(a6, q3.x, e2[6]); fma2(a7, q3.y, e2[7]);                         \
        _Pragma("unroll")                                                     \
        for (int k = 1; k < 8; ++k) {                                         \
            ulonglong2 r0 = pv[4 * k];                                        \
            ulonglong2 r1 = pv[4 * k + 1];                                    \
            ulonglong2 r2 = pv[4 * k + 2];                                    \
            ulonglong2 r3 = pv[4 * k + 3];                                    \
            fma2(a0, r0.x, e2[8 * k]);     fma2(a1, r0.y, e2[8 * k + 1]);     \
            fma2(a2, r1.x, e2[8 * k + 2]); fma2(a3, r1.y, e2[8 * k + 3]);     \
            fma2(a4, r2.x, e2[8 * k + 4]); fma2(a5, r2.y, e2[8 * k + 5]);     \
            fma2(a6, r3.x, e2[8 * k + 6]); fma2(a7, r3.y, e2[8 * k + 7]);     \
        }                                                                     \
        /* prefetch fills the dependency-tail gap; clamped, branchless */     \
        {                                                                     \
            int tp = (T_IDX) + 3; tp = tp < T_ - 1 ? tp : T_ - 1;             \
            eC = __expf(eb[(size_t)tp * K_ + j]);                             \
        }                                                                     \
        POST                                                                  \
        a0 = add2(a0, a1); a2 = add2(a2, a3);                                 \
        a4 = add2(a4, a5); a6 = add2(a6, a7);                                 \
        a0 = add2(a0, a2); a4 = add2(a4, a6);                                 \
        a0 = add2(a0, a4);                                                    \
        float2 sp = unpack2(a0);                                              \
        float s = sp.x + sp.y;                                                \
        p = mk ? s * eemx : p;                                                \
        (PWR)[j] = p;                                                         \
        __syncthreads();                                                      \
    }

    // prologue: steps 1..3 (step t reads (t+1)&1, writes t&1)
    CRF_STEP(1, pb0, pb1, m1, {})
    CRF_STEP(2, pb1, pb0, m2, {})
    CRF_STEP(3, pb0, pb1, m3, {})

    // main: blocks of 4 steps, t = 4, 8, ..., 1020
    int4 mk4n;
    for (int t = 4; t < T_; t += 4) {
        CRF_STEP(t, pb1, pb0, mk4.x, {
            int tn = t + 4; tn = tn < T_ - 4 ? tn : T_ - 4;
            mk4n = *(const int4*)(mb + tn);
        })
        CRF_STEP(t + 1, pb0, pb1, mk4.y, {})
        CRF_STEP(t + 2, pb1, pb0, mk4.z, {})
        CRF_STEP(t + 3, pb0, pb1, mk4.w, { mk4 = mk4n; })
    }
#undef CRF_STEP

    // logZ = ln2*kacc + log(sum_j p_j * exp(end_j))
    float v = p * __expf(endv[j]);
    float ws = warp_sum(v);
    if ((j & 31) == 0) wred[j >> 5] = ws;
    __syncthreads();
    if (j == 0) {
        float sm = (wred[0] + wred[1]) + (wred[2] + wred[3]);
        g_logz[b] = LN2 * (float)kacc + __logf(sm);
    }
}

// Final: mean over batches of (logZ - gold), fixed-order tree reduction.
__global__ void crf_finish(float* __restrict__ out) {
    __shared__ float sm[B_];
    int i = threadIdx.x;
    sm[i] = g_logz[i] - g_gold[i];
    __syncthreads();
    #pragma unroll
    for (int s = 128; s > 0; s >>= 1) {
        if (i < s) sm[i] += sm[i + s];
        __syncthreads();
    }
    if (i == 0) out[0] = sm[0] * (1.0f / B_);
}

extern "C" void kernel_launch(void* const* d_in, const int* in_sizes, int n_in,
                              void* d_out, int out_size) {
    const float* emis   = (const float*)d_in[0];
    const int* tags     = (const int*)d_in[1];
    const int* mask     = (const int*)d_in[2];
    const float* start  = (const float*)d_in[3];
    const float* endv   = (const float*)d_in[4];
    const float* trans  = (const float*)d_in[5];
    float* out = (float*)d_out;

    crf_main<<<2 * B_, K_>>>(emis, tags, mask, start, endv, trans);
    crf_finish<<<1, B_>>>(out);
}